// round 15
// baseline (speedup 1.0000x reference)
#include <cuda_runtime.h>
#include <cuda_fp16.h>
#include <mma.h>
#include <cstdint>

using namespace nvcuda;

#define NN 100000
#define NN_PAD 100032           // padded so unguarded 64-row wmma stores stay in-bounds
#define EE 1600000
#define HH 128
#define GG 1000
#define CC 10
#define LL 3
#define BN_EPS 1e-5f

// ---------------- scratch (static device globals; no allocation) ----------------
__device__ __half d_gh[NN_PAD * HH];  // fp16 dinv-scaled GEMM output (gather array)
__device__ __half d_preh[NN * HH];    // fp16 pre-BN activations
__device__ __half d_wh[LL * HH * HH]; // fp16 transposed weights: d_wh[l][n*128+k] = W[l][k][n]
__device__ float  d_dinv[NN];
__device__ int    d_deg[NN];
__device__ int    d_rowstart[NN];
__device__ int    d_cursor[NN];
__device__ int    d_colsrc[EE];
__device__ float  d_bnsum[HH];
__device__ float  d_bnsq[HH];
__device__ float  d_scale[HH];
__device__ float  d_shift[HH];
__device__ float  d_pooled[GG * HH];
__device__ int    d_cnt[GG];
__device__ int    d_bsum[128];        // scan block sums (98 used)

// ---------------- graph preprocessing ----------------
// launch idx 0: zero degrees + transpose/convert all 3 layer weights to fp16
__global__ void k_zero_deg(const float* __restrict__ conv_w) {
    int i = blockIdx.x * 256 + threadIdx.x;
    if (i < NN) d_deg[i] = 0;
    if (i < LL * HH * HH) {
        int l = i >> 14;
        int rem = i & 16383;
        int n = rem >> 7;
        int k = rem & 127;
        d_wh[(l << 14) + n * 128 + k] = __float2half(conv_w[(l << 14) + k * 128 + n]);
    }
}

__global__ void k_count(const int* __restrict__ ei) {
    int e = blockIdx.x * 256 + threadIdx.x;
    if (e >= EE) return;
    atomicAdd(&d_deg[ei[EE + e]], 1);
}

__global__ void k_scan1() {  // per-block degree sum; also computes dinv
    __shared__ int sh[1024];
    int i = blockIdx.x * 1024 + threadIdx.x;
    int v = (i < NN) ? d_deg[i] : 0;
    if (i < NN) d_dinv[i] = rsqrtf(1.0f + (float)v);
    sh[threadIdx.x] = v;
    __syncthreads();
    for (int s = 512; s > 0; s >>= 1) {
        if (threadIdx.x < s) sh[threadIdx.x] += sh[threadIdx.x + s];
        __syncthreads();
    }
    if (threadIdx.x == 0) d_bsum[blockIdx.x] = sh[0];
}

__global__ void k_scan2(int nb) {
    if (threadIdx.x == 0 && blockIdx.x == 0) {
        int acc = 0;
        for (int b = 0; b < nb; b++) { int v = d_bsum[b]; d_bsum[b] = acc; acc += v; }
    }
}

__global__ void k_scan3() {
    __shared__ int sh[1024];
    int tid = threadIdx.x;
    int i = blockIdx.x * 1024 + tid;
    int v = (i < NN) ? d_deg[i] : 0;
    sh[tid] = v;
    __syncthreads();
    for (int off = 1; off < 1024; off <<= 1) {
        int tv = (tid >= off) ? sh[tid - off] : 0;
        __syncthreads();
        sh[tid] += tv;
        __syncthreads();
    }
    if (i < NN) {
        int excl = sh[tid] - v + d_bsum[blockIdx.x];
        d_rowstart[i] = excl;
        d_cursor[i]   = excl;
    }
}

__global__ void k_fill(const int* __restrict__ ei) {
    int e = blockIdx.x * 256 + threadIdx.x;
    if (e >= EE) return;
    int dd = ei[EE + e];
    int pos = atomicAdd(&d_cursor[dd], 1);
    d_colsrc[pos] = ei[e];
}

// ---------------- wmma GEMM: d_gh = fp16( (dinv ⊙ bn_relu(A)) @ W ) ----------------
// dinv row-scaling folded into the A-tile (D·(A@W) == (D·A)@W).
// 64 rows x 128 cols per CTA, 256 threads = 8 warps; warp tile 32x32 (2x2 frags).
// Epilogue: f32 acc frags -> f16 acc frags elementwise, store_matrix_sync direct to gmem.
#define GR 64
#define ALD 136
#define SM_SSC 0
#define SM_SSH 512
#define SM_A   1024
#define SM_B   (1024 + GR * ALD * 2)                 // 18432
#define MMA_SMEM_BYTES (1024 + GR * ALD * 2 + 128 * ALD * 2)  // 53,248 B -> 4 CTAs/SM

__global__ __launch_bounds__(256) void k_gemm_mma(const float* __restrict__ x0, int layer) {
    extern __shared__ char smem[];
    float* ssc = (float*)(smem + SM_SSC);
    float* ssh = (float*)(smem + SM_SSH);
    __half* As = (__half*)(smem + SM_A);
    __half* Bs = (__half*)(smem + SM_B);

    int t = threadIdx.x;
    int wid = t >> 5;
    int blockRow = blockIdx.x * GR;

    if (t < 128) {
        ssc[t] = (layer != 0) ? d_scale[t] : 1.0f;
        ssh[t] = (layer != 0) ? d_shift[t] : 0.0f;
    }

    // B tile: d_wh[layer] (fp16 [n][k]) -> Bs[n*ALD + k]. 2048 uint4 / 256 = 8 each.
    {
        const uint4* src = (const uint4*)(d_wh + layer * HH * HH);
#pragma unroll
        for (int i = 0; i < 8; i++) {
            int f = t + i * 256;
            int n = f >> 4;
            int k8 = (f & 15) * 8;
            *(uint4*)&Bs[n * ALD + k8] = src[f];
        }
    }
    __syncthreads();  // ssc/ssh ready before A transform

    // A tile (64 rows), with dinv row-scaling folded in
    if (layer == 0) {
        // x fp32 -> fp16 * dinv: 2048 float4 / 256 = 8 each
#pragma unroll
        for (int i = 0; i < 8; i++) {
            int f = t + i * 256;
            int r = f >> 5;
            int k4 = (f & 31) * 4;
            int gr = blockRow + r;
            float4 a = make_float4(0.f, 0.f, 0.f, 0.f);
            float dv = 0.f;
            if (gr < NN) {
                a = *(const float4*)&x0[gr * HH + k4];
                dv = d_dinv[gr];
            }
            __half2 h0 = __floats2half2_rn(a.x * dv, a.y * dv);
            __half2 h1 = __floats2half2_rn(a.z * dv, a.w * dv);
            uint2 u;
            u.x = *(uint32_t*)&h0;
            u.y = *(uint32_t*)&h1;
            *(uint2*)&As[r * ALD + k4] = u;
        }
    } else {
        // d_preh fp16 with affine+relu+dinv folded: 1024 uint4 / 256 = 4 each
        const uint4* src = (const uint4*)d_preh;
#pragma unroll
        for (int i = 0; i < 4; i++) {
            int f = t + i * 256;
            int r = f >> 4;
            int k8 = (f & 15) * 8;
            int gr = blockRow + r;
            uint4 v = make_uint4(0u, 0u, 0u, 0u);
            if (gr < NN) {
                float dv = d_dinv[gr];
                v = src[gr * 16 + (f & 15)];
                __half2* hp = (__half2*)&v;
#pragma unroll
                for (int p = 0; p < 4; p++) {
                    float2 f2 = __half22float2(hp[p]);
                    int kk = k8 + p * 2;
                    f2.x = fmaxf(fmaf(f2.x, ssc[kk], ssh[kk]), 0.f) * dv;
                    f2.y = fmaxf(fmaf(f2.y, ssc[kk + 1], ssh[kk + 1]), 0.f) * dv;
                    hp[p] = __floats2half2_rn(f2.x, f2.y);
                }
            }
            *(uint4*)&As[r * ALD + k8] = v;
        }
    }
    __syncthreads();

    // MMA: warp tile 32x32. mbase = (wid&1)*32, nbase = (wid>>1)*32.
    wmma::fragment<wmma::accumulator, 16, 16, 16, float> acc[2][2];
#pragma unroll
    for (int i = 0; i < 2; i++)
#pragma unroll
        for (int j = 0; j < 2; j++) wmma::fill_fragment(acc[i][j], 0.0f);

    int mbase = (wid & 1) * 32;
    int nbase = (wid >> 1) * 32;
#pragma unroll
    for (int k0 = 0; k0 < 128; k0 += 16) {
        wmma::fragment<wmma::matrix_a, 16, 16, 16, __half, wmma::row_major> af[2];
        wmma::load_matrix_sync(af[0], As + mbase * ALD + k0, ALD);
        wmma::load_matrix_sync(af[1], As + (mbase + 16) * ALD + k0, ALD);
        wmma::fragment<wmma::matrix_b, 16, 16, 16, __half, wmma::col_major> bf[2];
        wmma::load_matrix_sync(bf[0], Bs + nbase * ALD + k0, ALD);
        wmma::load_matrix_sync(bf[1], Bs + (nbase + 16) * ALD + k0, ALD);
#pragma unroll
        for (int i = 0; i < 2; i++)
#pragma unroll
            for (int j = 0; j < 2; j++)
                wmma::mma_sync(acc[i][j], af[i], bf[j], acc[i][j]);
    }

    // epilogue: f32 -> f16 fragments, store direct to gmem (d_gh padded to NN_PAD)
#pragma unroll
    for (int i = 0; i < 2; i++)
#pragma unroll
        for (int j = 0; j < 2; j++) {
            wmma::fragment<wmma::accumulator, 16, 16, 16, __half> hacc;
#pragma unroll
            for (int e = 0; e < hacc.num_elements; e++)
                hacc.x[e] = __float2half(acc[i][j].x[e]);
            wmma::store_matrix_sync(
                d_gh + (size_t)(blockRow + mbase + 16 * i) * HH + nbase + 16 * j,
                hacc, HH, wmma::mem_row_major);
        }
}

// ---------------- aggregation + combine + BN stats (fp16 gathers) ----------------
#define AGG_ROWS 64
__global__ __launch_bounds__(256) void k_agg(const float* __restrict__ bias) {
    int t = threadIdx.x;
    int j = t & 63;
    int grp = t >> 6;
    int base = blockIdx.x * AGG_ROWS;
    const __half2* g2 = (const __half2*)d_gh;
    __half2* preh2 = (__half2*)d_preh;
    float bx = bias[2 * j], by = bias[2 * j + 1];
    float lsx = 0.f, lsy = 0.f, lqx = 0.f, lqy = 0.f;
#pragma unroll 1
    for (int r = grp; r < AGG_ROWS; r += 4) {
        int d = base + r;
        if (d >= NN) break;
        float2 sf = __half22float2(g2[d * 64 + j]);  // self-loop (already dinv-scaled)
        float a0x = sf.x, a0y = sf.y;
        float a1x = 0.f, a1y = 0.f, a2x = 0.f, a2y = 0.f, a3x = 0.f, a3y = 0.f;
        int s0 = d_rowstart[d];
        int cnt = d_deg[d];
        int e = 0;
        for (; e + 3 < cnt; e += 4) {
            int s1 = d_colsrc[s0 + e];
            int s2 = d_colsrc[s0 + e + 1];
            int s3 = d_colsrc[s0 + e + 2];
            int s4 = d_colsrc[s0 + e + 3];
            float2 v1 = __half22float2(g2[s1 * 64 + j]);
            float2 v2 = __half22float2(g2[s2 * 64 + j]);
            float2 v3 = __half22float2(g2[s3 * 64 + j]);
            float2 v4 = __half22float2(g2[s4 * 64 + j]);
            a0x += v1.x; a0y += v1.y;
            a1x += v2.x; a1y += v2.y;
            a2x += v3.x; a2y += v3.y;
            a3x += v4.x; a3y += v4.y;
        }
        for (; e < cnt; e++) {
            float2 v = __half22float2(g2[d_colsrc[s0 + e] * 64 + j]);
            a0x += v.x; a0y += v.y;
        }
        float dv = d_dinv[d];
        float vx = fmaf(dv, (a0x + a1x) + (a2x + a3x), bx);
        float vy = fmaf(dv, (a0y + a1y) + (a2y + a3y), by);
        preh2[d * 64 + j] = __floats2half2_rn(vx, vy);
        lsx += vx; lqx = fmaf(vx, vx, lqx);
        lsy += vy; lqy = fmaf(vy, vy, lqy);
    }
    atomicAdd(&d_bnsum[2 * j], lsx);
    atomicAdd(&d_bnsum[2 * j + 1], lsy);
    atomicAdd(&d_bnsq[2 * j], lqx);
    atomicAdd(&d_bnsq[2 * j + 1], lqy);
}

__global__ void k_bnfin(const float* __restrict__ gamma, const float* __restrict__ beta) {
    int j = threadIdx.x;
    float mean = d_bnsum[j] * (1.0f / NN);
    float var  = d_bnsq[j] * (1.0f / NN) - mean * mean;
    float s = gamma[j] * rsqrtf(var + BN_EPS);
    d_scale[j] = s;
    d_shift[j] = beta[j] - mean * s;
    // zero-after-read: steady-state invariant under graph replay
    d_bnsum[j] = 0.f;
    d_bnsq[j]  = 0.f;
}

// ---------------- global mean pool (batch is sorted) ----------------
#define POOL_R 256
__global__ void k_pool(const int* __restrict__ batch) {
    int j = threadIdx.x;  // 0..127
    int base = blockIdx.x * POOL_R;
    if (base >= NN) return;
    int end = base + POOL_R;
    if (end > NN) end = NN;
    int cur = batch[base];
    float acc = 0.f;
    int run = 0;
    float sc = d_scale[j], sh = d_shift[j];
    for (int row = base; row < end; row++) {
        int b = batch[row];
        if (b != cur) {
            atomicAdd(&d_pooled[cur * HH + j], acc);
            if (j == 0) atomicAdd(&d_cnt[cur], run);
            acc = 0.f; run = 0; cur = b;
        }
        float v = __half2float(d_preh[(size_t)row * HH + j]);
        v = fmaxf(fmaf(v, sc, sh), 0.f);
        acc += v;
        run++;
    }
    atomicAdd(&d_pooled[cur * HH + j], acc);
    if (j == 0) atomicAdd(&d_cnt[cur], run);
}

// ---------------- classifier MLP (zeroes its pooled row after reading) ----------------
__global__ void k_mlp(const float* __restrict__ w1, const float* __restrict__ b1,
                      const float* __restrict__ w2, const float* __restrict__ b2,
                      float* __restrict__ out) {
    __shared__ float p[128];
    __shared__ float z[64];
    int t = threadIdx.x;  // 0..63
    int g = blockIdx.x;
    float c = fmaxf((float)d_cnt[g], 1.0f);
    float inv = 1.0f / c;
    p[t]      = d_pooled[g * HH + t] * inv;
    p[t + 64] = d_pooled[g * HH + 64 + t] * inv;
    __syncthreads();
    d_pooled[g * HH + t] = 0.f;
    d_pooled[g * HH + 64 + t] = 0.f;
    if (t == 0) d_cnt[g] = 0;
    float a = b1[t];
#pragma unroll 8
    for (int k = 0; k < 128; k++) a = fmaf(p[k], w1[k * 64 + t], a);
    z[t] = fmaxf(a, 0.f);
    __syncthreads();
    if (t < CC) {
        float o = b2[t];
#pragma unroll
        for (int q = 0; q < 64; q++) o = fmaf(z[q], w2[q * CC + t], o);
        out[g * CC + t] = o;
    }
}

// ---------------- launch ----------------
extern "C" void kernel_launch(void* const* d_in, const int* in_sizes, int n_in,
                              void* d_out, int out_size) {
    const float* x      = (const float*)d_in[0];
    const float* conv_w = (const float*)d_in[1];
    const float* conv_b = (const float*)d_in[2];
    const float* bng    = (const float*)d_in[3];
    const float* bnb    = (const float*)d_in[4];
    const float* w1     = (const float*)d_in[5];
    const float* b1     = (const float*)d_in[6];
    const float* w2     = (const float*)d_in[7];
    const float* b2     = (const float*)d_in[8];
    const int*   ei     = (const int*)d_in[9];
    const int*   batch  = (const int*)d_in[10];
    float* out = (float*)d_out;

    cudaFuncSetAttribute(k_gemm_mma, cudaFuncAttributeMaxDynamicSharedMemorySize,
                         MMA_SMEM_BYTES);

    const int NB_SCAN = (NN + 1023) / 1024;            // 98
    const int GEMM_GRID = (NN + GR - 1) / GR;          // 1563

    // idx 0..3 arranged so ncu capture (launch index 3) profiles the wmma GEMM
    k_zero_deg<<<(NN + 255) / 256, 256>>>(conv_w);     // 0: deg=0 + W fp16 transpose
    k_count<<<(EE + 255) / 256, 256>>>(ei);            // 1
    k_scan1<<<NB_SCAN, 1024>>>();                      // 2: block sums + dinv
    k_gemm_mma<<<GEMM_GRID, 256, MMA_SMEM_BYTES>>>(x, 0);  // 3: layer-0 GEMM (profiled)
    k_scan2<<<1, 32>>>(NB_SCAN);                       // 4
    k_scan3<<<NB_SCAN, 1024>>>();                      // 5
    k_fill<<<(EE + 255) / 256, 256>>>(ei);             // 6

    for (int l = 0; l < LL; l++) {
        if (l > 0)
            k_gemm_mma<<<GEMM_GRID, 256, MMA_SMEM_BYTES>>>(x, l);
        k_agg<<<(NN + AGG_ROWS - 1) / AGG_ROWS, 256>>>(conv_b + l * HH);
        k_bnfin<<<1, 128>>>(bng + l * HH, bnb + l * HH);
    }

    k_pool<<<(NN + POOL_R - 1) / POOL_R, 128>>>(batch);
    k_mlp<<<GG, 64>>>(w1, b1, w2, b2, out);
}

// round 17
// speedup vs baseline: 1.2778x; 1.2778x over previous
#include <cuda_runtime.h>
#include <cuda_fp16.h>
#include <mma.h>
#include <cstdint>

using namespace nvcuda;

#define NN 100000
#define NN_PAD 100032           // padded so unguarded 64-row wmma stores stay in-bounds
#define EE 1600000
#define HH 128
#define GG 1000
#define CC 10
#define LL 3
#define BN_EPS 1e-5f
#define NB_SCAN 98              // ceil(100000/1024)
#define WT_BLOCKS 48            // 49152 weight elems / 1024
#define GEMM_GRID 1563          // ceil(NN/64)
#define FILL_GRID 6250          // ceil(EE/256)

// ---------------- scratch (static device globals; no allocation) ----------------
__device__ __half d_gh[NN_PAD * HH];  // fp16 dinv-scaled GEMM output (gather array)
__device__ __half d_preh[NN * HH];    // fp16 pre-BN activations
__device__ __half d_wh[LL * HH * HH]; // fp16 transposed weights: d_wh[l][n*128+k] = W[l][k][n]
__device__ float  d_dinv[NN];
__device__ int    d_deg[NN];
__device__ int    d_rowstart[NN];
__device__ int    d_cursor[NN];
__device__ int    d_colsrc[EE];
__device__ float  d_bnsum[HH];
__device__ float  d_bnsq[HH];
__device__ float  d_scale[HH];
__device__ float  d_shift[HH];
__device__ float  d_pooled[GG * HH];
__device__ int    d_cnt[GG];
__device__ unsigned long long d_scanflag[128];  // epoch-tagged lookback flags
__device__ unsigned int d_epoch;

// ---------------- launch 0: count degrees (deg zeroed by k_pool of prev call) ----
__global__ void k_count(const int* __restrict__ ei) {
    if (blockIdx.x == 0 && threadIdx.x == 0) d_epoch = d_epoch + 1;  // new scan epoch
    int e = blockIdx.x * 256 + threadIdx.x;
    if (e >= EE) return;
    atomicAdd(&d_deg[ei[EE + e]], 1);
}

// ---------------- launch 1: single-pass scan (decoupled lookback) + dinv + W fp16 --
__device__ __forceinline__ unsigned long long scan_pack(unsigned epoch, unsigned st,
                                                        unsigned val) {
    return ((unsigned long long)(epoch & 0x3FFFFFFFu) << 34) |
           ((unsigned long long)st << 32) | (unsigned long long)val;
}

__global__ __launch_bounds__(1024) void k_scan(const float* __restrict__ conv_w) {
    int b = blockIdx.x;
    if (b >= NB_SCAN) {  // W transpose/convert blocks
        int i = (b - NB_SCAN) * 1024 + threadIdx.x;  // 0..49151
        int l = i >> 14;
        int rem = i & 16383;
        int n = rem >> 7;
        int k = rem & 127;
        d_wh[(l << 14) + n * 128 + k] = __float2half(conv_w[(l << 14) + k * 128 + n]);
        return;
    }
    __shared__ int sh[1024];
    __shared__ int sbase;
    unsigned epoch = d_epoch;
    int tid = threadIdx.x;
    int i = b * 1024 + tid;
    int v = (i < NN) ? d_deg[i] : 0;
    if (i < NN) d_dinv[i] = rsqrtf(1.0f + (float)v);
    sh[tid] = v;
    __syncthreads();
    for (int off = 1; off < 1024; off <<= 1) {  // Hillis-Steele inclusive
        int tv = (tid >= off) ? sh[tid - off] : 0;
        __syncthreads();
        sh[tid] += tv;
        __syncthreads();
    }
    int incl = sh[tid];
    if (tid == 0) {
        int total = sh[1023];
        if (b == 0) {
            atomicExch(&d_scanflag[0], scan_pack(epoch, 2u, (unsigned)total));
            sbase = 0;
        } else {
            atomicExch(&d_scanflag[b], scan_pack(epoch, 1u, (unsigned)total));
            long long running = 0;
            int j = b - 1;
            while (true) {
                unsigned long long f = atomicAdd(&d_scanflag[j], 0ULL);
                if (((unsigned)(f >> 34) & 0x3FFFFFFFu) != (epoch & 0x3FFFFFFFu)) continue;
                unsigned st = (unsigned)(f >> 32) & 3u;
                unsigned val = (unsigned)(f & 0xFFFFFFFFu);
                running += val;
                if (st == 2u) break;
                j--;
            }
            sbase = (int)running;
            atomicExch(&d_scanflag[b],
                       scan_pack(epoch, 2u, (unsigned)(running + total)));
        }
    }
    __syncthreads();
    if (i < NN) {
        int excl = sbase + incl - v;
        d_rowstart[i] = excl;
        d_cursor[i]   = excl;
    }
}

// ---------------- wmma GEMM tile: d_gh = fp16( (dinv ⊙ bn_relu(A)) @ W ) ----------
// 64 rows x 128 cols per tile, 256 threads = 8 warps; warp tile 32x32 (2x2 frags).
#define GR 64
#define ALD 136
#define SM_SSC 0
#define SM_SSH 512
#define SM_A   1024
#define SM_B   (1024 + GR * ALD * 2)                 // 18432
#define MMA_SMEM_BYTES (1024 + GR * ALD * 2 + 128 * ALD * 2)  // 53,248 B -> 4 CTAs/SM

__device__ __forceinline__ void gemm_tile(const float* __restrict__ x0, int layer,
                                          int tileIdx) {
    extern __shared__ char smem[];
    float* ssc = (float*)(smem + SM_SSC);
    float* ssh = (float*)(smem + SM_SSH);
    __half* As = (__half*)(smem + SM_A);
    __half* Bs = (__half*)(smem + SM_B);

    int t = threadIdx.x;
    int wid = t >> 5;
    int blockRow = tileIdx * GR;

    if (t < 128) {
        ssc[t] = (layer != 0) ? d_scale[t] : 1.0f;
        ssh[t] = (layer != 0) ? d_shift[t] : 0.0f;
    }

    // B tile: d_wh[layer] (fp16 [n][k]) -> Bs[n*ALD + k]. 2048 uint4 / 256 = 8 each.
    {
        const uint4* src = (const uint4*)(d_wh + layer * HH * HH);
#pragma unroll
        for (int i = 0; i < 8; i++) {
            int f = t + i * 256;
            int n = f >> 4;
            int k8 = (f & 15) * 8;
            *(uint4*)&Bs[n * ALD + k8] = src[f];
        }
    }
    __syncthreads();  // ssc/ssh ready before A transform

    // A tile (64 rows), with dinv row-scaling folded in
    if (layer == 0) {
#pragma unroll
        for (int i = 0; i < 8; i++) {
            int f = t + i * 256;
            int r = f >> 5;
            int k4 = (f & 31) * 4;
            int gr = blockRow + r;
            float4 a = make_float4(0.f, 0.f, 0.f, 0.f);
            float dv = 0.f;
            if (gr < NN) {
                a = *(const float4*)&x0[gr * HH + k4];
                dv = d_dinv[gr];
            }
            __half2 h0 = __floats2half2_rn(a.x * dv, a.y * dv);
            __half2 h1 = __floats2half2_rn(a.z * dv, a.w * dv);
            uint2 u;
            u.x = *(uint32_t*)&h0;
            u.y = *(uint32_t*)&h1;
            *(uint2*)&As[r * ALD + k4] = u;
        }
    } else {
        const uint4* src = (const uint4*)d_preh;
#pragma unroll
        for (int i = 0; i < 4; i++) {
            int f = t + i * 256;
            int r = f >> 4;
            int k8 = (f & 15) * 8;
            int gr = blockRow + r;
            uint4 v = make_uint4(0u, 0u, 0u, 0u);
            if (gr < NN) {
                float dv = d_dinv[gr];
                v = src[gr * 16 + (f & 15)];
                __half2* hp = (__half2*)&v;
#pragma unroll
                for (int p = 0; p < 4; p++) {
                    float2 f2 = __half22float2(hp[p]);
                    int kk = k8 + p * 2;
                    f2.x = fmaxf(fmaf(f2.x, ssc[kk], ssh[kk]), 0.f) * dv;
                    f2.y = fmaxf(fmaf(f2.y, ssc[kk + 1], ssh[kk + 1]), 0.f) * dv;
                    hp[p] = __floats2half2_rn(f2.x, f2.y);
                }
            }
            *(uint4*)&As[r * ALD + k8] = v;
        }
    }
    __syncthreads();

    wmma::fragment<wmma::accumulator, 16, 16, 16, float> acc[2][2];
#pragma unroll
    for (int i = 0; i < 2; i++)
#pragma unroll
        for (int j = 0; j < 2; j++) wmma::fill_fragment(acc[i][j], 0.0f);

    int mbase = (wid & 1) * 32;
    int nbase = (wid >> 1) * 32;
#pragma unroll
    for (int k0 = 0; k0 < 128; k0 += 16) {
        wmma::fragment<wmma::matrix_a, 16, 16, 16, __half, wmma::row_major> af[2];
        wmma::load_matrix_sync(af[0], As + mbase * ALD + k0, ALD);
        wmma::load_matrix_sync(af[1], As + (mbase + 16) * ALD + k0, ALD);
        wmma::fragment<wmma::matrix_b, 16, 16, 16, __half, wmma::col_major> bf[2];
        wmma::load_matrix_sync(bf[0], Bs + nbase * ALD + k0, ALD);
        wmma::load_matrix_sync(bf[1], Bs + (nbase + 16) * ALD + k0, ALD);
#pragma unroll
        for (int i = 0; i < 2; i++)
#pragma unroll
            for (int j = 0; j < 2; j++)
                wmma::mma_sync(acc[i][j], af[i], bf[j], acc[i][j]);
    }

    // epilogue: f32 -> f16 fragments, store direct to gmem (d_gh padded to NN_PAD)
#pragma unroll
    for (int i = 0; i < 2; i++)
#pragma unroll
        for (int j = 0; j < 2; j++) {
            wmma::fragment<wmma::accumulator, 16, 16, 16, __half> hacc;
#pragma unroll
            for (int e = 0; e < hacc.num_elements; e++)
                hacc.x[e] = __float2half(acc[i][j].x[e]);
            wmma::store_matrix_sync(
                d_gh + (size_t)(blockRow + mbase + 16 * i) * HH + nbase + 16 * j,
                hacc, HH, wmma::mem_row_major);
        }
}

// launch 2: fused layer-0 GEMM (blocks [0,GEMM_GRID)) + CSR fill (rest) — independent
__global__ __launch_bounds__(256) void k_fillgemm(const float* __restrict__ x0,
                                                  const int* __restrict__ ei) {
    if (blockIdx.x < GEMM_GRID) {
        gemm_tile(x0, 0, blockIdx.x);
    } else {
        int e = (blockIdx.x - GEMM_GRID) * 256 + threadIdx.x;
        if (e < EE) {
            int dd = ei[EE + e];
            int pos = atomicAdd(&d_cursor[dd], 1);
            d_colsrc[pos] = ei[e];
        }
    }
}

// standalone GEMM for layers 1,2
__global__ __launch_bounds__(256) void k_gemm_mma(const float* __restrict__ x0, int layer) {
    gemm_tile(x0, layer, blockIdx.x);
}

// ---------------- aggregation + combine + BN stats (fp16 gathers) ----------------
// body identical to the R13/R15 passing kernels (no in-kernel deg zeroing).
#define AGG_ROWS 64
__global__ __launch_bounds__(256) void k_agg(const float* __restrict__ bias) {
    int t = threadIdx.x;
    int j = t & 63;
    int grp = t >> 6;
    int base = blockIdx.x * AGG_ROWS;
    const __half2* g2 = (const __half2*)d_gh;
    __half2* preh2 = (__half2*)d_preh;
    float bx = bias[2 * j], by = bias[2 * j + 1];
    float lsx = 0.f, lsy = 0.f, lqx = 0.f, lqy = 0.f;
#pragma unroll 1
    for (int r = grp; r < AGG_ROWS; r += 4) {
        int d = base + r;
        if (d >= NN) break;
        float2 sf = __half22float2(g2[d * 64 + j]);  // self-loop (already dinv-scaled)
        float a0x = sf.x, a0y = sf.y;
        float a1x = 0.f, a1y = 0.f, a2x = 0.f, a2y = 0.f, a3x = 0.f, a3y = 0.f;
        int s0 = d_rowstart[d];
        int cnt = d_deg[d];
        int e = 0;
        for (; e + 3 < cnt; e += 4) {
            int s1 = d_colsrc[s0 + e];
            int s2 = d_colsrc[s0 + e + 1];
            int s3 = d_colsrc[s0 + e + 2];
            int s4 = d_colsrc[s0 + e + 3];
            float2 v1 = __half22float2(g2[s1 * 64 + j]);
            float2 v2 = __half22float2(g2[s2 * 64 + j]);
            float2 v3 = __half22float2(g2[s3 * 64 + j]);
            float2 v4 = __half22float2(g2[s4 * 64 + j]);
            a0x += v1.x; a0y += v1.y;
            a1x += v2.x; a1y += v2.y;
            a2x += v3.x; a2y += v3.y;
            a3x += v4.x; a3y += v4.y;
        }
        for (; e < cnt; e++) {
            float2 v = __half22float2(g2[d_colsrc[s0 + e] * 64 + j]);
            a0x += v.x; a0y += v.y;
        }
        float dv = d_dinv[d];
        float vx = fmaf(dv, (a0x + a1x) + (a2x + a3x), bx);
        float vy = fmaf(dv, (a0y + a1y) + (a2y + a3y), by);
        preh2[d * 64 + j] = __floats2half2_rn(vx, vy);
        lsx += vx; lqx = fmaf(vx, vx, lqx);
        lsy += vy; lqy = fmaf(vy, vy, lqy);
    }
    atomicAdd(&d_bnsum[2 * j], lsx);
    atomicAdd(&d_bnsum[2 * j + 1], lsy);
    atomicAdd(&d_bnsq[2 * j], lqx);
    atomicAdd(&d_bnsq[2 * j + 1], lqy);
}

__global__ void k_bnfin(const float* __restrict__ gamma, const float* __restrict__ beta) {
    int j = threadIdx.x;
    float mean = d_bnsum[j] * (1.0f / NN);
    float var  = d_bnsq[j] * (1.0f / NN) - mean * mean;
    float s = gamma[j] * rsqrtf(var + BN_EPS);
    d_scale[j] = s;
    d_shift[j] = beta[j] - mean * s;
    // zero-after-read: steady-state invariant under graph replay
    d_bnsum[j] = 0.f;
    d_bnsq[j]  = 0.f;
}

// ---------------- global mean pool (batch is sorted); also zeroes d_deg ----------
#define POOL_R 256
__global__ void k_pool(const int* __restrict__ batch) {
    int j = threadIdx.x;  // 0..127
    int base = blockIdx.x * POOL_R;
    if (base >= NN) return;
    // zero d_deg for next call (runs after the last k_agg read of d_deg)
    {
        int z0 = base + j;
        int z1 = base + 128 + j;
        if (z0 < NN) d_deg[z0] = 0;
        if (z1 < NN) d_deg[z1] = 0;
    }
    int end = base + POOL_R;
    if (end > NN) end = NN;
    int cur = batch[base];
    float acc = 0.f;
    int run = 0;
    float sc = d_scale[j], sh = d_shift[j];
    for (int row = base; row < end; row++) {
        int b = batch[row];
        if (b != cur) {
            atomicAdd(&d_pooled[cur * HH + j], acc);
            if (j == 0) atomicAdd(&d_cnt[cur], run);
            acc = 0.f; run = 0; cur = b;
        }
        float v = __half2float(d_preh[(size_t)row * HH + j]);
        v = fmaxf(fmaf(v, sc, sh), 0.f);
        acc += v;
        run++;
    }
    atomicAdd(&d_pooled[cur * HH + j], acc);
    if (j == 0) atomicAdd(&d_cnt[cur], run);
}

// ---------------- classifier MLP (zeroes its pooled row after reading) ----------------
__global__ void k_mlp(const float* __restrict__ w1, const float* __restrict__ b1,
                      const float* __restrict__ w2, const float* __restrict__ b2,
                      float* __restrict__ out) {
    __shared__ float p[128];
    __shared__ float z[64];
    int t = threadIdx.x;  // 0..63
    int g = blockIdx.x;
    float c = fmaxf((float)d_cnt[g], 1.0f);
    float inv = 1.0f / c;
    p[t]      = d_pooled[g * HH + t] * inv;
    p[t + 64] = d_pooled[g * HH + 64 + t] * inv;
    __syncthreads();
    d_pooled[g * HH + t] = 0.f;
    d_pooled[g * HH + 64 + t] = 0.f;
    if (t == 0) d_cnt[g] = 0;
    float a = b1[t];
#pragma unroll 8
    for (int k = 0; k < 128; k++) a = fmaf(p[k], w1[k * 64 + t], a);
    z[t] = fmaxf(a, 0.f);
    __syncthreads();
    if (t < CC) {
        float o = b2[t];
#pragma unroll
        for (int q = 0; q < 64; q++) o = fmaf(z[q], w2[q * CC + t], o);
        out[g * CC + t] = o;
    }
}

// ---------------- launch ----------------
extern "C" void kernel_launch(void* const* d_in, const int* in_sizes, int n_in,
                              void* d_out, int out_size) {
    const float* x      = (const float*)d_in[0];
    const float* conv_w = (const float*)d_in[1];
    const float* conv_b = (const float*)d_in[2];
    const float* bng    = (const float*)d_in[3];
    const float* bnb    = (const float*)d_in[4];
    const float* w1     = (const float*)d_in[5];
    const float* b1     = (const float*)d_in[6];
    const float* w2     = (const float*)d_in[7];
    const float* b2     = (const float*)d_in[8];
    const int*   ei     = (const int*)d_in[9];
    const int*   batch  = (const int*)d_in[10];
    float* out = (float*)d_out;

    cudaFuncSetAttribute(k_fillgemm, cudaFuncAttributeMaxDynamicSharedMemorySize,
                         MMA_SMEM_BYTES);
    cudaFuncSetAttribute(k_gemm_mma, cudaFuncAttributeMaxDynamicSharedMemorySize,
                         MMA_SMEM_BYTES);

    const int AGG_GRID = (NN + AGG_ROWS - 1) / AGG_ROWS;  // 1563

    // 0: degree count (deg zeroed by prev call's k_pool; zero-init on first call)
    k_count<<<FILL_GRID, 256>>>(ei);
    // 1: single-pass scan + dinv + rowstart/cursor, plus W fp16 transpose blocks
    k_scan<<<NB_SCAN + WT_BLOCKS, 1024>>>(conv_w);
    // 2: layer-0 GEMM fused with CSR fill (independent; overlap)
    k_fillgemm<<<GEMM_GRID + FILL_GRID, 256, MMA_SMEM_BYTES>>>(x, ei);
    // 3: layer-0 aggregation  <-- ncu capture index 3: profiles k_agg
    k_agg<<<AGG_GRID, 256>>>(conv_b);
    k_bnfin<<<1, 128>>>(bng, bnb);

    for (int l = 1; l < LL; l++) {
        k_gemm_mma<<<GEMM_GRID, 256, MMA_SMEM_BYTES>>>(x, l);
        k_agg<<<AGG_GRID, 256>>>(conv_b + l * HH);
        k_bnfin<<<1, 128>>>(bng + l * HH, bnb + l * HH);
    }

    k_pool<<<(NN + POOL_R - 1) / POOL_R, 128>>>(batch);
    k_mlp<<<GG, 64>>>(w1, b1, w2, b2, out);
}